// round 4
// baseline (speedup 1.0000x reference)
#include <cuda_runtime.h>

#define DD 8
#define HH 64
#define TPB 128

// ---- dynamic shared memory layout (float offsets; all 16B aligned) ----
#define OW1T 0        // [9][64]   W1^T ([d][j], d==8 is t row)
#define OB1  576      // [64]
#define OW2T 640      // [64][64]  W2^T ([k][j]) forward
#define OW2  4736     // [64][64]  W2   ([j][k]) backward
#define OB2  8832     // [64]
#define OW3T 8896     // [64][8]   W3^T ([k][d])
#define OB3  9408     // [8] (+8 pad)
#define OW1S 9424     // [64] sum_{d<8} W1[k][d]
#define OW3S 9488     // [64] sum_d W3[d][j]
#define OH   9552     // [64][TPB] h1 state (thread-id fast)
#define OG   17744    // [64][TPB] h2 / g_a2 state
#define SMEM_FLOATS 25936
#define SMEM_BYTES  (SMEM_FLOATS * 4)

// tanh(x) = 1 - 2/(exp2(2*log2e*x)+1); saturates correctly, ~1e-6 rel err.
__device__ __forceinline__ float fast_tanh(float x) {
    float e; asm("ex2.approx.f32 %0, %1;" : "=f"(e) : "f"(x * 2.88539008177792681472f));
    float r; asm("rcp.approx.f32 %0, %1;" : "=f"(r) : "f"(e + 1.0f));
    return fmaf(-2.0f, r, 1.0f);
}

__global__ void __launch_bounds__(TPB, 2)
cnf_kernel(const float* __restrict__ x0,
           const float* __restrict__ W1g,   // [64][9]
           const float* __restrict__ b1g,   // [64]
           const float* __restrict__ W2g,   // [64][64]
           const float* __restrict__ b2g,   // [64]
           const float* __restrict__ W3g,   // [8][64]
           const float* __restrict__ b3g,   // [8]
           const int*   __restrict__ nsp,
           float* __restrict__ out, int n)
{
    extern __shared__ float dsm[];

    const int tid = threadIdx.x;

    // ---------------- cooperative weight init ----------------
    for (int idx = tid; idx < HH * HH; idx += TPB) {
        int j = idx >> 6, k = idx & 63;
        float v = W2g[idx];
        dsm[OW2 + j * HH + k]  = v;   // [j][k]
        dsm[OW2T + k * HH + j] = v;   // [k][j]
    }
    for (int idx = tid; idx < HH * (DD + 1); idx += TPB) {
        int j = idx / (DD + 1), d = idx % (DD + 1);
        dsm[OW1T + d * HH + j] = W1g[idx];
    }
    for (int idx = tid; idx < HH * DD; idx += TPB) {
        int d = idx >> 6, k = idx & 63;
        dsm[OW3T + k * DD + d] = W3g[idx];
    }
    for (int idx = tid; idx < HH; idx += TPB) {
        dsm[OB1 + idx] = b1g[idx];
        dsm[OB2 + idx] = b2g[idx];
        float s1 = 0.f;
        for (int d = 0; d < DD; d++) s1 += W1g[idx * (DD + 1) + d];
        dsm[OW1S + idx] = s1;
        float s3 = 0.f;
        for (int d = 0; d < DD; d++) s3 += W3g[d * HH + idx];
        dsm[OW3S + idx] = s3;
    }
    if (tid < DD) dsm[OB3 + tid] = b3g[tid];
    __syncthreads();

    float* __restrict__ hb = &dsm[OH];   // hb[k*TPB + tid] : this thread's h1[k]
    float* __restrict__ gb = &dsm[OG];   // gb[j*TPB + tid] : this thread's h2[j] / g_a2[j]

    const int row = blockIdx.x * TPB + tid;
    const bool active = row < n;
    const int lrow = active ? row : 0;

    float x0r, x1r, x2r, x3r, x4r, x5r, x6r, x7r;
    {
        float4 v0 = ((const float4*)x0)[lrow * 2];
        float4 v1 = ((const float4*)x0)[lrow * 2 + 1];
        x0r = v0.x; x1r = v0.y; x2r = v0.z; x3r = v0.w;
        x4r = v1.x; x5r = v1.y; x6r = v1.z; x7r = v1.w;
    }
    float ld = 0.f;

    const int nsteps = nsp ? *nsp : 100;
    const float dt = 1.0f / (float)nsteps;

    #pragma unroll 1
    for (int i = 0; i < nsteps; i++) {
        const float t = (float)i * dt;

        // Two forwards: pass 0 at (x,t) updates x via layer 3;
        // pass 1 at (x_new,t) leaves h1 in hb and h2 in gb for the backward.
        #pragma unroll 1
        for (int pass = 0; pass < 2; pass++) {
            // ---- layer 1: hb = tanh(W1 @ [x; t] + b1) ----
            #pragma unroll 1
            for (int c = 0; c < HH; c += 8) {
                float a0, a1, a2, a3, a4, a5, a6, a7;
                {
                    float4 b0 = *(const float4*)&dsm[OB1 + c];
                    float4 b1v = *(const float4*)&dsm[OB1 + c + 4];
                    a0 = b0.x; a1 = b0.y; a2 = b0.z; a3 = b0.w;
                    a4 = b1v.x; a5 = b1v.y; a6 = b1v.z; a7 = b1v.w;
                }
                #define L1ROW(d, s)                                              \
                {                                                                \
                    float4 w0 = *(const float4*)&dsm[OW1T + (d) * HH + c];       \
                    float4 w1 = *(const float4*)&dsm[OW1T + (d) * HH + c + 4];   \
                    a0 = fmaf(s, w0.x, a0); a1 = fmaf(s, w0.y, a1);              \
                    a2 = fmaf(s, w0.z, a2); a3 = fmaf(s, w0.w, a3);              \
                    a4 = fmaf(s, w1.x, a4); a5 = fmaf(s, w1.y, a5);              \
                    a6 = fmaf(s, w1.z, a6); a7 = fmaf(s, w1.w, a7);              \
                }
                L1ROW(0, x0r) L1ROW(1, x1r) L1ROW(2, x2r) L1ROW(3, x3r)
                L1ROW(4, x4r) L1ROW(5, x5r) L1ROW(6, x6r) L1ROW(7, x7r)
                L1ROW(8, t)
                #undef L1ROW
                hb[(c + 0) * TPB + tid] = fast_tanh(a0);
                hb[(c + 1) * TPB + tid] = fast_tanh(a1);
                hb[(c + 2) * TPB + tid] = fast_tanh(a2);
                hb[(c + 3) * TPB + tid] = fast_tanh(a3);
                hb[(c + 4) * TPB + tid] = fast_tanh(a4);
                hb[(c + 5) * TPB + tid] = fast_tanh(a5);
                hb[(c + 6) * TPB + tid] = fast_tanh(a6);
                hb[(c + 7) * TPB + tid] = fast_tanh(a7);
            }
            // ---- layer 2: gb = tanh(W2 @ h + b2) ----
            #pragma unroll 1
            for (int c = 0; c < HH; c += 8) {
                float a0, a1, a2, a3, a4, a5, a6, a7;
                {
                    float4 b0 = *(const float4*)&dsm[OB2 + c];
                    float4 b1v = *(const float4*)&dsm[OB2 + c + 4];
                    a0 = b0.x; a1 = b0.y; a2 = b0.z; a3 = b0.w;
                    a4 = b1v.x; a5 = b1v.y; a6 = b1v.z; a7 = b1v.w;
                }
                #pragma unroll 8
                for (int k = 0; k < HH; k++) {
                    const float s = hb[k * TPB + tid];
                    float4 w0 = *(const float4*)&dsm[OW2T + k * HH + c];
                    float4 w1 = *(const float4*)&dsm[OW2T + k * HH + c + 4];
                    a0 = fmaf(s, w0.x, a0); a1 = fmaf(s, w0.y, a1);
                    a2 = fmaf(s, w0.z, a2); a3 = fmaf(s, w0.w, a3);
                    a4 = fmaf(s, w1.x, a4); a5 = fmaf(s, w1.y, a5);
                    a6 = fmaf(s, w1.z, a6); a7 = fmaf(s, w1.w, a7);
                }
                gb[(c + 0) * TPB + tid] = fast_tanh(a0);
                gb[(c + 1) * TPB + tid] = fast_tanh(a1);
                gb[(c + 2) * TPB + tid] = fast_tanh(a2);
                gb[(c + 3) * TPB + tid] = fast_tanh(a3);
                gb[(c + 4) * TPB + tid] = fast_tanh(a4);
                gb[(c + 5) * TPB + tid] = fast_tanh(a5);
                gb[(c + 6) * TPB + tid] = fast_tanh(a6);
                gb[(c + 7) * TPB + tid] = fast_tanh(a7);
            }
            // ---- layer 3 (pass 0 only): x += dt * (W3 @ g + b3) ----
            if (pass == 0) {
                float a0, a1, a2, a3, a4, a5, a6, a7;
                {
                    float4 b0 = *(const float4*)&dsm[OB3];
                    float4 b1v = *(const float4*)&dsm[OB3 + 4];
                    a0 = b0.x; a1 = b0.y; a2 = b0.z; a3 = b0.w;
                    a4 = b1v.x; a5 = b1v.y; a6 = b1v.z; a7 = b1v.w;
                }
                #pragma unroll 8
                for (int k = 0; k < HH; k++) {
                    const float s = gb[k * TPB + tid];
                    float4 w0 = *(const float4*)&dsm[OW3T + k * DD];
                    float4 w1 = *(const float4*)&dsm[OW3T + k * DD + 4];
                    a0 = fmaf(s, w0.x, a0); a1 = fmaf(s, w0.y, a1);
                    a2 = fmaf(s, w0.z, a2); a3 = fmaf(s, w0.w, a3);
                    a4 = fmaf(s, w1.x, a4); a5 = fmaf(s, w1.y, a5);
                    a6 = fmaf(s, w1.z, a6); a7 = fmaf(s, w1.w, a7);
                }
                x0r = fmaf(dt, a0, x0r); x1r = fmaf(dt, a1, x1r);
                x2r = fmaf(dt, a2, x2r); x3r = fmaf(dt, a3, x3r);
                x4r = fmaf(dt, a4, x4r); x5r = fmaf(dt, a5, x5r);
                x6r = fmaf(dt, a6, x6r); x7r = fmaf(dt, a7, x7r);
            }
        }

        // ---------------- backward (VJP, ones cotangent) ----------------
        // gb[j] := w3s[j] * (1 - h2[j]^2)
        #pragma unroll 8
        for (int j = 0; j < HH; j++) {
            float w = dsm[OW3S + j];
            float gj = gb[j * TPB + tid];
            gb[j * TPB + tid] = fmaf(-(gj * w), gj, w);
        }
        // gh1[k] = sum_j g_a2[j] * W2[j][k]; fold through tanh' and w1s into ld
        float s0 = 0.f, s1 = 0.f;
        #pragma unroll 1
        for (int c = 0; c < HH; c += 8) {
            float a0 = 0.f, a1 = 0.f, a2 = 0.f, a3 = 0.f;
            float a4 = 0.f, a5 = 0.f, a6 = 0.f, a7 = 0.f;
            #pragma unroll 8
            for (int j = 0; j < HH; j++) {
                const float s = gb[j * TPB + tid];
                float4 w0 = *(const float4*)&dsm[OW2 + j * HH + c];
                float4 w1 = *(const float4*)&dsm[OW2 + j * HH + c + 4];
                a0 = fmaf(s, w0.x, a0); a1 = fmaf(s, w0.y, a1);
                a2 = fmaf(s, w0.z, a2); a3 = fmaf(s, w0.w, a3);
                a4 = fmaf(s, w1.x, a4); a5 = fmaf(s, w1.y, a5);
                a6 = fmaf(s, w1.z, a6); a7 = fmaf(s, w1.w, a7);
            }
            float4 u0 = *(const float4*)&dsm[OW1S + c];
            float4 u1 = *(const float4*)&dsm[OW1S + c + 4];
            #define LDFOLD(acc, wk, kk, sreg)                                    \
            {                                                                    \
                float hh = hb[(c + kk) * TPB + tid];                             \
                float tt = (acc) * (wk);                                         \
                sreg += tt; sreg = fmaf(-(tt * hh), hh, sreg);                   \
            }
            LDFOLD(a0, u0.x, 0, s0) LDFOLD(a1, u0.y, 1, s1)
            LDFOLD(a2, u0.z, 2, s0) LDFOLD(a3, u0.w, 3, s1)
            LDFOLD(a4, u1.x, 4, s0) LDFOLD(a5, u1.y, 5, s1)
            LDFOLD(a6, u1.z, 6, s0) LDFOLD(a7, u1.w, 7, s1)
            #undef LDFOLD
        }
        ld = fmaf(dt, s0 + s1, ld);
    }

    if (active) {
        float4 v0, v1;
        v0.x = x0r; v0.y = x1r; v0.z = x2r; v0.w = x3r;
        v1.x = x4r; v1.y = x5r; v1.z = x6r; v1.w = x7r;
        ((float4*)out)[row * 2]     = v0;
        ((float4*)out)[row * 2 + 1] = v1;
        out[n * DD + row] = ld;
    }
}

extern "C" void kernel_launch(void* const* d_in, const int* in_sizes, int n_in,
                              void* d_out, int out_size) {
    const float* x0 = (const float*)d_in[0];
    const float* W1 = (const float*)d_in[1];
    const float* b1 = (const float*)d_in[2];
    const float* W2 = (const float*)d_in[3];
    const float* b2 = (const float*)d_in[4];
    const float* W3 = (const float*)d_in[5];
    const float* b3 = (const float*)d_in[6];
    const int* nsp = (n_in > 7) ? (const int*)d_in[7] : nullptr;

    cudaFuncSetAttribute(cnf_kernel,
                         cudaFuncAttributeMaxDynamicSharedMemorySize, SMEM_BYTES);

    int n = in_sizes[0] / DD;
    int blocks = (n + TPB - 1) / TPB;
    cnf_kernel<<<blocks, TPB, SMEM_BYTES>>>(x0, W1, b1, W2, b2, W3, b3, nsp,
                                            (float*)d_out, n);
}

// round 5
// speedup vs baseline: 1.1771x; 1.1771x over previous
#include <cuda_runtime.h>

#define DD 8
#define HH 64
#define TPB 64
#define RPC 128   // rows per CTA = TPB * 2

// ---- dynamic shared memory layout (float offsets; all 16B aligned) ----
#define OW1T 0        // [9][64]   W1^T ([d][j], d==8 is t row)
#define OB1  576      // [64]
#define OW2T 640      // [64][64]  W2^T ([k][j]) forward
#define OW2  4736     // [64][64]  W2   ([j][k]) backward
#define OB2  8832     // [64]
#define OW3T 8896     // [64][8]   W3^T ([k][d])
#define OB3  9408     // [8] (+8 pad)
#define OW1S 9424     // [64] sum_{d<8} W1[k][d]
#define OW3S 9488     // [64] sum_d W3[d][j]
#define OH   9552     // [64][128] h1 state: col = tid (row A) / 64+tid (row B)
#define OG   17744    // [64][128] h2 / g_a2 state
#define SMEM_FLOATS 25936
#define SMEM_BYTES  (SMEM_FLOATS * 4)

typedef unsigned long long u64;
typedef ulonglong2 u64x2;

__device__ __forceinline__ u64 pk2(float a, float b) {
    u64 r; asm("mov.b64 %0, {%1,%2};" : "=l"(r) : "f"(a), "f"(b)); return r;
}
__device__ __forceinline__ void up2(u64 v, float& a, float& b) {
    asm("mov.b64 {%0,%1}, %2;" : "=f"(a), "=f"(b) : "l"(v));
}
__device__ __forceinline__ u64 f2fma(u64 a, u64 b, u64 c) {
    u64 d; asm("fma.rn.f32x2 %0, %1, %2, %3;" : "=l"(d) : "l"(a), "l"(b), "l"(c)); return d;
}
// tanh(x) = 1 - 2/(exp2(2*log2e*x)+1); saturates correctly, ~1e-6 rel err.
__device__ __forceinline__ float fast_tanh(float x) {
    float e; asm("ex2.approx.f32 %0, %1;" : "=f"(e) : "f"(x * 2.88539008177792681472f));
    float r; asm("rcp.approx.f32 %0, %1;" : "=f"(r) : "f"(e + 1.0f));
    return fmaf(-2.0f, r, 1.0f);
}

// 8 packed FMAs: 2 rows (p0/p1 broadcasts) x 8 outputs (wA,wB = 2x LDS.128)
#define MAC8() \
    a0 = f2fma(p0, wA.x, a0); a1 = f2fma(p0, wA.y, a1); \
    a2 = f2fma(p0, wB.x, a2); a3 = f2fma(p0, wB.y, a3); \
    b0 = f2fma(p1, wA.x, b0); b1 = f2fma(p1, wA.y, b1); \
    b2 = f2fma(p1, wB.x, b2); b3 = f2fma(p1, wB.y, b3);

// unpack 4 accums -> tanh -> 8 state stores at column COL
#define TSTORE4(A0, A1, A2, A3, OFF, COL) \
    { float e, o; \
      up2(A0, e, o); dsm[(OFF)+(c+0)*RPC+(COL)] = fast_tanh(e); dsm[(OFF)+(c+1)*RPC+(COL)] = fast_tanh(o); \
      up2(A1, e, o); dsm[(OFF)+(c+2)*RPC+(COL)] = fast_tanh(e); dsm[(OFF)+(c+3)*RPC+(COL)] = fast_tanh(o); \
      up2(A2, e, o); dsm[(OFF)+(c+4)*RPC+(COL)] = fast_tanh(e); dsm[(OFF)+(c+5)*RPC+(COL)] = fast_tanh(o); \
      up2(A3, e, o); dsm[(OFF)+(c+6)*RPC+(COL)] = fast_tanh(e); dsm[(OFF)+(c+7)*RPC+(COL)] = fast_tanh(o); }

__global__ void __launch_bounds__(TPB, 2)
cnf_kernel(const float* __restrict__ x0,
           const float* __restrict__ W1g,   // [64][9]
           const float* __restrict__ b1g,   // [64]
           const float* __restrict__ W2g,   // [64][64]
           const float* __restrict__ b2g,   // [64]
           const float* __restrict__ W3g,   // [8][64]
           const float* __restrict__ b3g,   // [8]
           const int*   __restrict__ nsp,
           float* __restrict__ out, int n)
{
    extern __shared__ float dsm[];
    const int tid = threadIdx.x;

    // ---------------- cooperative weight init ----------------
    for (int idx = tid; idx < HH * HH; idx += TPB) {
        int j = idx >> 6, k = idx & 63;
        float v = W2g[idx];
        dsm[OW2 + j * HH + k]  = v;   // [j][k]
        dsm[OW2T + k * HH + j] = v;   // [k][j]
    }
    for (int idx = tid; idx < HH * (DD + 1); idx += TPB) {
        int j = idx / (DD + 1), d = idx % (DD + 1);
        dsm[OW1T + d * HH + j] = W1g[idx];
    }
    for (int idx = tid; idx < HH * DD; idx += TPB) {
        int d = idx >> 6, k = idx & 63;
        dsm[OW3T + k * DD + d] = W3g[idx];
    }
    for (int idx = tid; idx < HH; idx += TPB) {
        dsm[OB1 + idx] = b1g[idx];
        dsm[OB2 + idx] = b2g[idx];
        float s1 = 0.f;
        for (int d = 0; d < DD; d++) s1 += W1g[idx * (DD + 1) + d];
        dsm[OW1S + idx] = s1;
        float s3 = 0.f;
        for (int d = 0; d < DD; d++) s3 += W3g[d * HH + idx];
        dsm[OW3S + idx] = s3;
    }
    if (tid < DD) dsm[OB3 + tid] = b3g[tid];
    __syncthreads();

    const int base = blockIdx.x * RPC;
    const int rA = base + tid;          // row A
    const int rB = base + TPB + tid;    // row B
    const bool actA = rA < n, actB = rB < n;
    const int lA = actA ? rA : 0, lB = actB ? rB : 0;

    float xa0, xa1, xa2, xa3, xa4, xa5, xa6, xa7;
    float xb0, xb1, xb2, xb3, xb4, xb5, xb6, xb7;
    {
        float4 v0 = ((const float4*)x0)[lA * 2];
        float4 v1 = ((const float4*)x0)[lA * 2 + 1];
        xa0 = v0.x; xa1 = v0.y; xa2 = v0.z; xa3 = v0.w;
        xa4 = v1.x; xa5 = v1.y; xa6 = v1.z; xa7 = v1.w;
        float4 w0 = ((const float4*)x0)[lB * 2];
        float4 w1 = ((const float4*)x0)[lB * 2 + 1];
        xb0 = w0.x; xb1 = w0.y; xb2 = w0.z; xb3 = w0.w;
        xb4 = w1.x; xb5 = w1.y; xb6 = w1.z; xb7 = w1.w;
    }
    float lda = 0.f, ldb = 0.f;

    const int nsteps = nsp ? *nsp : 100;
    const float dt = 1.0f / (float)nsteps;

    #pragma unroll 1
    for (int i = 0; i < nsteps; i++) {
        const float t = (float)i * dt;

        #pragma unroll 1
        for (int pass = 0; pass < 2; pass++) {
            // ---- layer 1: OH = tanh(W1 @ [x; t] + b1) ----
            #pragma unroll 1
            for (int c = 0; c < HH; c += 8) {
                const u64x2 biA = *(const u64x2*)&dsm[OB1 + c];
                const u64x2 biB = *(const u64x2*)&dsm[OB1 + c + 4];
                u64 a0 = biA.x, a1 = biA.y, a2 = biB.x, a3 = biB.y;
                u64 b0 = biA.x, b1 = biA.y, b2 = biB.x, b3 = biB.y;
                #define L1ROW(d, sa, sb) { \
                    const u64 p0 = pk2(sa, sa), p1 = pk2(sb, sb); \
                    const u64x2 wA = *(const u64x2*)&dsm[OW1T + (d) * HH + c]; \
                    const u64x2 wB = *(const u64x2*)&dsm[OW1T + (d) * HH + c + 4]; \
                    MAC8() }
                L1ROW(0, xa0, xb0) L1ROW(1, xa1, xb1) L1ROW(2, xa2, xb2) L1ROW(3, xa3, xb3)
                L1ROW(4, xa4, xb4) L1ROW(5, xa5, xb5) L1ROW(6, xa6, xb6) L1ROW(7, xa7, xb7)
                L1ROW(8, t, t)
                #undef L1ROW
                TSTORE4(a0, a1, a2, a3, OH, tid)
                TSTORE4(b0, b1, b2, b3, OH, TPB + tid)
            }
            // ---- layer 2: OG = tanh(W2 @ h + b2) ----
            #pragma unroll 1
            for (int c = 0; c < HH; c += 8) {
                const u64x2 biA = *(const u64x2*)&dsm[OB2 + c];
                const u64x2 biB = *(const u64x2*)&dsm[OB2 + c + 4];
                u64 a0 = biA.x, a1 = biA.y, a2 = biB.x, a3 = biB.y;
                u64 b0 = biA.x, b1 = biA.y, b2 = biB.x, b3 = biB.y;
                #pragma unroll 8
                for (int k = 0; k < HH; k++) {
                    const float sa = dsm[OH + k * RPC + tid];
                    const float sb = dsm[OH + k * RPC + TPB + tid];
                    const u64 p0 = pk2(sa, sa), p1 = pk2(sb, sb);
                    const u64x2 wA = *(const u64x2*)&dsm[OW2T + k * HH + c];
                    const u64x2 wB = *(const u64x2*)&dsm[OW2T + k * HH + c + 4];
                    MAC8()
                }
                TSTORE4(a0, a1, a2, a3, OG, tid)
                TSTORE4(b0, b1, b2, b3, OG, TPB + tid)
            }
            // ---- layer 3 (pass 0 only): x += dt * (W3 @ h2 + b3) ----
            if (pass == 0) {
                const u64x2 biA = *(const u64x2*)&dsm[OB3];
                const u64x2 biB = *(const u64x2*)&dsm[OB3 + 4];
                u64 a0 = biA.x, a1 = biA.y, a2 = biB.x, a3 = biB.y;
                u64 b0 = biA.x, b1 = biA.y, b2 = biB.x, b3 = biB.y;
                #pragma unroll 8
                for (int k = 0; k < HH; k++) {
                    const float sa = dsm[OG + k * RPC + tid];
                    const float sb = dsm[OG + k * RPC + TPB + tid];
                    const u64 p0 = pk2(sa, sa), p1 = pk2(sb, sb);
                    const u64x2 wA = *(const u64x2*)&dsm[OW3T + k * DD];
                    const u64x2 wB = *(const u64x2*)&dsm[OW3T + k * DD + 4];
                    MAC8()
                }
                float e, o;
                up2(a0, e, o); xa0 = fmaf(dt, e, xa0); xa1 = fmaf(dt, o, xa1);
                up2(a1, e, o); xa2 = fmaf(dt, e, xa2); xa3 = fmaf(dt, o, xa3);
                up2(a2, e, o); xa4 = fmaf(dt, e, xa4); xa5 = fmaf(dt, o, xa5);
                up2(a3, e, o); xa6 = fmaf(dt, e, xa6); xa7 = fmaf(dt, o, xa7);
                up2(b0, e, o); xb0 = fmaf(dt, e, xb0); xb1 = fmaf(dt, o, xb1);
                up2(b1, e, o); xb2 = fmaf(dt, e, xb2); xb3 = fmaf(dt, o, xb3);
                up2(b2, e, o); xb4 = fmaf(dt, e, xb4); xb5 = fmaf(dt, o, xb5);
                up2(b3, e, o); xb6 = fmaf(dt, e, xb6); xb7 = fmaf(dt, o, xb7);
            }
        }

        // ---------------- backward (VJP, ones cotangent) ----------------
        // OG[j] := w3s[j] * (1 - h2[j]^2)
        #pragma unroll 8
        for (int j = 0; j < HH; j++) {
            const float w = dsm[OW3S + j];
            const float ga = dsm[OG + j * RPC + tid];
            const float gv = dsm[OG + j * RPC + TPB + tid];
            dsm[OG + j * RPC + tid]       = fmaf(-(ga * w), ga, w);
            dsm[OG + j * RPC + TPB + tid] = fmaf(-(gv * w), gv, w);
        }
        // gh1[k] = sum_j g_a2[j] * W2[j][k]; fold tanh' and w1s into ld
        float sa0 = 0.f, sa1 = 0.f, sb0 = 0.f, sb1 = 0.f;
        #pragma unroll 1
        for (int c = 0; c < HH; c += 8) {
            u64 a0 = 0ull, a1 = 0ull, a2 = 0ull, a3 = 0ull;
            u64 b0 = 0ull, b1 = 0ull, b2 = 0ull, b3 = 0ull;
            #pragma unroll 8
            for (int j = 0; j < HH; j++) {
                const float sa = dsm[OG + j * RPC + tid];
                const float sb = dsm[OG + j * RPC + TPB + tid];
                const u64 p0 = pk2(sa, sa), p1 = pk2(sb, sb);
                const u64x2 wA = *(const u64x2*)&dsm[OW2 + j * HH + c];
                const u64x2 wB = *(const u64x2*)&dsm[OW2 + j * HH + c + 4];
                MAC8()
            }
            const float4 u0 = *(const float4*)&dsm[OW1S + c];
            const float4 u1 = *(const float4*)&dsm[OW1S + c + 4];
            #define LDFOLD(ACC, COL, SREG0, SREG1, W0, W1, K0) { \
                float e, o; up2(ACC, e, o); \
                { float hh = dsm[OH + (K0) * RPC + (COL)]; float tt = e * (W0); \
                  SREG0 += tt; SREG0 = fmaf(-(tt * hh), hh, SREG0); } \
                { float hh = dsm[OH + ((K0) + 1) * RPC + (COL)]; float tt = o * (W1); \
                  SREG1 += tt; SREG1 = fmaf(-(tt * hh), hh, SREG1); } }
            LDFOLD(a0, tid, sa0, sa1, u0.x, u0.y, c + 0)
            LDFOLD(a1, tid, sa0, sa1, u0.z, u0.w, c + 2)
            LDFOLD(a2, tid, sa0, sa1, u1.x, u1.y, c + 4)
            LDFOLD(a3, tid, sa0, sa1, u1.z, u1.w, c + 6)
            LDFOLD(b0, TPB + tid, sb0, sb1, u0.x, u0.y, c + 0)
            LDFOLD(b1, TPB + tid, sb0, sb1, u0.z, u0.w, c + 2)
            LDFOLD(b2, TPB + tid, sb0, sb1, u1.x, u1.y, c + 4)
            LDFOLD(b3, TPB + tid, sb0, sb1, u1.z, u1.w, c + 6)
            #undef LDFOLD
        }
        lda = fmaf(dt, sa0 + sa1, lda);
        ldb = fmaf(dt, sb0 + sb1, ldb);
    }

    if (actA) {
        float4 v0, v1;
        v0.x = xa0; v0.y = xa1; v0.z = xa2; v0.w = xa3;
        v1.x = xa4; v1.y = xa5; v1.z = xa6; v1.w = xa7;
        ((float4*)out)[rA * 2] = v0;
        ((float4*)out)[rA * 2 + 1] = v1;
        out[n * DD + rA] = lda;
    }
    if (actB) {
        float4 v0, v1;
        v0.x = xb0; v0.y = xb1; v0.z = xb2; v0.w = xb3;
        v1.x = xb4; v1.y = xb5; v1.z = xb6; v1.w = xb7;
        ((float4*)out)[rB * 2] = v0;
        ((float4*)out)[rB * 2 + 1] = v1;
        out[n * DD + rB] = ldb;
    }
}

extern "C" void kernel_launch(void* const* d_in, const int* in_sizes, int n_in,
                              void* d_out, int out_size) {
    const float* x0 = (const float*)d_in[0];
    const float* W1 = (const float*)d_in[1];
    const float* b1 = (const float*)d_in[2];
    const float* W2 = (const float*)d_in[3];
    const float* b2 = (const float*)d_in[4];
    const float* W3 = (const float*)d_in[5];
    const float* b3 = (const float*)d_in[6];
    const int* nsp = (n_in > 7) ? (const int*)d_in[7] : nullptr;

    cudaFuncSetAttribute(cnf_kernel,
                         cudaFuncAttributeMaxDynamicSharedMemorySize, SMEM_BYTES);

    int n = in_sizes[0] / DD;
    int blocks = (n + RPC - 1) / RPC;
    cnf_kernel<<<blocks, TPB, SMEM_BYTES>>>(x0, W1, b1, W2, b2, W3, b3, nsp,
                                            (float*)d_out, n);
}